// round 15
// baseline (speedup 1.0000x reference)
#include <cuda_runtime.h>
#include <cuda_fp16.h>

#define Bb 8
#define Nn 4096
#define Cc 128
#define Kk 20

// ------------------------- scratch (device globals, no allocs) -------------
__device__ int    g_knn[Bb*Nn*Kk];        // 20 neighbor indices per point (global b*N+n space)
__device__ float  g_center[Bb*Cc*Nn];     // Wc @ leaky(p)         [b][o][n]
__device__ __half g_hT[Bb*Nn*Cc];         // (Wg @ leaky(p))^T in fp16  [b][n][o]

// ------------------------- KNN (2 lanes/query, balanced grid) --------------
// R11/R14 structure; drain is SYSTOLIC-2: two staged items traverse the
// 21-stage sort network in lockstep offset by one stage (item1 hits stage
// s-1 after item0 already passed it) -> bitwise-identical to sequential
// insertion, but the two 84-cyc FMNMX carry chains overlap.
#define KNN_INF  3.402823466e38f
#define KTHR 256
#define KSTG 20
#define QPBLK 111
#define BPB 37

__device__ __forceinline__ void stg1(float& dsS, int& ixS, float& cd, int& ci) {
    bool t   = cd < dsS;                 // strict: earlier insert wins ties
    float mn = fminf(cd, dsS);
    float mx = fmaxf(cd, dsS);
    int  ni  = t ? ci : ixS;
    ci       = t ? ixS : ci;
    dsS = mn; ixS = ni; cd = mx;
}

__device__ __forceinline__ void pair_ins(float (&ds)[21], int (&ix)[21],
                                         float cd, int ci) {
    #pragma unroll
    for (int s = 0; s < 21; ++s) stg1(ds[s], ix[s], cd, ci);
}

// two items, systolic: exact sequential semantics, overlapped chains
__device__ __forceinline__ void pair_ins2(float (&ds)[21], int (&ix)[21],
                                          float c0, int i0, float c1, int i1) {
    stg1(ds[0], ix[0], c0, i0);
    #pragma unroll
    for (int s = 1; s < 21; ++s) {
        stg1(ds[s],     ix[s],     c0, i0);
        stg1(ds[s - 1], ix[s - 1], c1, i1);
    }
    stg1(ds[20], ix[20], c1, i1);
}

__device__ __forceinline__ unsigned long long dj_pack(float d, int j) {
    unsigned long long r;
    asm("mov.b64 %0, {%1, %2};" : "=l"(r) : "r"(j), "f"(d));
    return r;
}
__device__ __forceinline__ void dj_unpack(unsigned long long v, float& d, int& j) {
    asm("mov.b64 {%0, %1}, %2;" : "=r"(j), "=f"(d) : "l"(v));
}

__global__ __launch_bounds__(KTHR, 2) void knn_kernel(const float* __restrict__ xyz) {
    extern __shared__ float sraw[];
    float4* tile = (float4*)sraw;                              // Nn float4 (64KB)
    unsigned long long* stg = (unsigned long long*)(sraw + Nn*4);  // KTHR*(KSTG+1) u64

    int tid  = threadIdx.x;
    int half = tid & 1;                                // candidate parity
    int qloc = tid >> 1;                               // 0..127 (slots; QPBLK used)
    int bib  = blockIdx.x % BPB;                       // block-in-batch 0..36
    int b    = blockIdx.x / BPB;
    int qstart = bib * QPBLK;
    int qcount = min(QPBLK, Nn - qstart);
    const float* px = xyz + b * 3 * Nn;

    for (int n = tid; n < Nn; n += KTHR) {
        float x = px[n], y = px[Nn + n], z = px[2*Nn + n];
        tile[n] = make_float4(x, y, z, fmaf(x, x, fmaf(y, y, z * z)));
    }
    __syncthreads();

    bool active = qloc < qcount;
    int selfn = qstart + (active ? qloc : 0);
    float4 me = tile[selfn];
    float mx = -2.f * me.x, my = -2.f * me.y, mz = -2.f * me.z;

    float ds[21]; int ix[21];
    #pragma unroll
    for (int s = 0; s < 21; ++s) { ds[s] = KNN_INF; ix[s] = 0; }
    float worst = active ? KNN_INF : -KNN_INF;         // idle: never qualifies
    int cnt = 0;
    unsigned long long* st = stg + tid * (KSTG + 1);

    #pragma unroll 1
    for (int i0 = 0; i0 < Nn/2; i0 += 8) {
        float dd[8]; int jj[8]; bool qf[8];
        #pragma unroll
        for (int u = 0; u < 8; ++u) {
            jj[u] = (i0 + u) * 2 + half;
            float4 c = tile[jj[u]];
            dd[u] = fmaf(mx, c.x, fmaf(my, c.y, fmaf(mz, c.z, c.w)));
            qf[u] = dd[u] < worst;
        }
        int cc = cnt;
        #pragma unroll
        for (int u = 0; u < 8; ++u) {
            if (qf[u]) st[cc] = dj_pack(dd[u], jj[u]);
            cc += qf[u];
        }
        cnt = cc;

        if (__any_sync(0xffffffffu, cnt >= KSTG - 8)) {
            int um = __reduce_max_sync(0xffffffffu, cnt);
            um = (um + 1) & ~1;                        // even; st[20] exists (KSTG+1)
            #pragma unroll 1
            for (int u = 0; u < um; u += 2) {
                float vd0, vd1; int vi0, vi1;
                dj_unpack(st[u],     vd0, vi0);
                dj_unpack(st[u + 1], vd1, vi1);
                pair_ins2(ds, ix,
                          (u     < cnt) ? vd0 : KNN_INF, vi0,
                          (u + 1 < cnt) ? vd1 : KNN_INF, vi1);
            }
            float wm = ds[20];
            float wp = __shfl_xor_sync(0xffffffffu, wm, 1);
            worst = active ? fminf(wm, wp) : -KNN_INF;
            cnt = 0;
        }
    }
    {   // final drain
        int um = __reduce_max_sync(0xffffffffu, cnt);
        um = (um + 1) & ~1;
        #pragma unroll 1
        for (int u = 0; u < um; u += 2) {
            float vd0, vd1; int vi0, vi1;
            dj_unpack(st[u],     vd0, vi0);
            dj_unpack(st[u + 1], vd1, vi1);
            pair_ins2(ds, ix,
                      (u     < cnt) ? vd0 : KNN_INF, vi0,
                      (u + 1 < cnt) ? vd1 : KNN_INF, vi1);
        }
    }

    // merge lane pair: snapshot partner's sorted list, insert w/ early break
    float od[21]; int oi[21];
    #pragma unroll
    for (int s = 0; s < 21; ++s) {
        od[s] = __shfl_xor_sync(0xffffffffu, ds[s], 1);
        oi[s] = __shfl_xor_sync(0xffffffffu, ix[s], 1);
    }
    #pragma unroll 1
    for (int s = 0; s < 21; ++s) {
        if (od[s] >= ds[20]) break;                    // od sorted: rest can't enter
        pair_ins(ds, ix, od[s], oi[s]);
    }

    if (half == 0 && active) {
        int gq = b * Nn + qstart + qloc;
        int base = b * Nn;
        #pragma unroll
        for (int s = 0; s < 20; ++s) g_knn[gq*Kk + s] = base + ix[s + 1];  // drop self
    }
}

// ------------------------- GEMM via mma.sync (HMMA fp16 -> f32) ------------
// grid (N/128, B, 2); z=0 -> center [b][o][n] f32; z=1 -> g_hT [b][n][o] fp16
#define WROW 136
#define PROW 132
#define GEMM_SMEM (128*WROW*2 + 128*PROW*2)

__global__ __launch_bounds__(256) void gemm_kernel(const float* __restrict__ points,
                                                   const float* __restrict__ Wc,
                                                   const float* __restrict__ Wg) {
    extern __shared__ char gsm[];
    __half* Wh = (__half*)gsm;                    // [128][WROW]
    __half* Pt = (__half*)(gsm + 128*WROW*2);     // [128 n][PROW c]
    int b = blockIdx.y, n0 = blockIdx.x * 128, which = blockIdx.z;
    const float* W = which ? Wg : Wc;
    const float* P = points + b * Cc * Nn;
    int tid  = threadIdx.x;
    int lane = tid & 31, warp = tid >> 5;
    int g = lane >> 2, tig = lane & 3;
    int warp_m = warp >> 2, warp_n = warp & 3;    // 2 x 4 warp grid

    #pragma unroll
    for (int i = 0; i < 16; ++i) {
        int v = tid + i * 256;
        int o = v >> 5, c4 = (v & 31) * 4;
        float4 w = *(const float4*)(W + o*Cc + c4);
        __half2* dst = (__half2*)&Wh[o*WROW + c4];
        dst[0] = __floats2half2_rn(w.x, w.y);
        dst[1] = __floats2half2_rn(w.z, w.w);
    }
    #pragma unroll
    for (int i = 0; i < 16; ++i) {
        int v = tid + i * 256;
        int c = v >> 5, n4 = (v & 31) * 4;
        float4 p = *(const float4*)(P + c*Nn + n0 + n4);
        float f[4] = {p.x, p.y, p.z, p.w};
        #pragma unroll
        for (int u = 0; u < 4; ++u) {
            float pv = fmaxf(f[u], 0.f) + 0.01f * fminf(f[u], 0.f);
            Pt[(n4 + u)*PROW + c] = __float2half(pv);
        }
    }
    __syncthreads();

    float acc[4][4][4];
    #pragma unroll
    for (int mf = 0; mf < 4; ++mf)
        #pragma unroll
        for (int nf = 0; nf < 4; ++nf)
            #pragma unroll
            for (int u = 0; u < 4; ++u) acc[mf][nf][u] = 0.f;

    int o0 = warp_m * 64, nb0 = warp_n * 32;
    #pragma unroll
    for (int ks = 0; ks < 128; ks += 16) {
        unsigned a[4][4], bf[4][2];
        #pragma unroll
        for (int mf = 0; mf < 4; ++mf) {
            const __half* base = &Wh[(o0 + mf*16 + g)*WROW + ks + tig*2];
            a[mf][0] = *(const unsigned*)base;
            a[mf][1] = *(const unsigned*)(base + 8*WROW);
            a[mf][2] = *(const unsigned*)(base + 8);
            a[mf][3] = *(const unsigned*)(base + 8*WROW + 8);
        }
        #pragma unroll
        for (int nf = 0; nf < 4; ++nf) {
            const __half* base = &Pt[(nb0 + nf*8 + g)*PROW + ks + tig*2];
            bf[nf][0] = *(const unsigned*)base;
            bf[nf][1] = *(const unsigned*)(base + 8);
        }
        #pragma unroll
        for (int mf = 0; mf < 4; ++mf)
            #pragma unroll
            for (int nf = 0; nf < 4; ++nf)
                asm volatile(
                    "mma.sync.aligned.m16n8k16.row.col.f32.f16.f16.f32 "
                    "{%0,%1,%2,%3}, {%4,%5,%6,%7}, {%8,%9}, {%0,%1,%2,%3};"
                    : "+f"(acc[mf][nf][0]), "+f"(acc[mf][nf][1]),
                      "+f"(acc[mf][nf][2]), "+f"(acc[mf][nf][3])
                    : "r"(a[mf][0]), "r"(a[mf][1]), "r"(a[mf][2]), "r"(a[mf][3]),
                      "r"(bf[nf][0]), "r"(bf[nf][1]));
    }

    if (which == 0) {
        #pragma unroll
        for (int mf = 0; mf < 4; ++mf)
            #pragma unroll
            for (int nf = 0; nf < 4; ++nf) {
                int o = o0 + mf*16 + g;
                int n = n0 + nb0 + nf*8 + tig*2;
                float* d0 = g_center + (b*Cc + o    )*Nn + n;
                float* d1 = g_center + (b*Cc + o + 8)*Nn + n;
                *(float2*)d0 = make_float2(acc[mf][nf][0], acc[mf][nf][1]);
                *(float2*)d1 = make_float2(acc[mf][nf][2], acc[mf][nf][3]);
            }
    } else {
        __syncthreads();
        __half* Ct = (__half*)gsm;                // [128 n][WROW o]
        #pragma unroll
        for (int mf = 0; mf < 4; ++mf)
            #pragma unroll
            for (int nf = 0; nf < 4; ++nf) {
                int ol = o0 + mf*16 + g;
                int nl = nb0 + nf*8 + tig*2;
                Ct[ nl     *WROW + ol    ] = __float2half(acc[mf][nf][0]);
                Ct[(nl + 1)*WROW + ol    ] = __float2half(acc[mf][nf][1]);
                Ct[ nl     *WROW + ol + 8] = __float2half(acc[mf][nf][2]);
                Ct[(nl + 1)*WROW + ol + 8] = __float2half(acc[mf][nf][3]);
            }
        __syncthreads();
        int row = tid >> 1, part = tid & 1;
        __half* dst = g_hT + ((size_t)(b*Nn + n0 + row))*Cc;
        #pragma unroll
        for (int q = 0; q < 8; ++q) {
            int c8 = (part*8 + q)*8;
            *(uint4*)(dst + c8) = *(uint4*)&Ct[row*WROW + c8];
        }
    }
}

// ------------------------- combine: gather-sum + center + bias + residual --
__global__ __launch_bounds__(256) void combine_kernel(const float* __restrict__ points,
                                                      const float* __restrict__ bc,
                                                      const float* __restrict__ bg,
                                                      float* __restrict__ out) {
    __shared__ float sm[32][133];     // [n_local][o], pad 133 -> conflict-free transpose
    __shared__ int   sidx[32*20];
    int b  = blockIdx.y;
    int n0 = blockIdx.x * 32;
    int tid = threadIdx.x;

    for (int u = tid; u < 32*20; u += 256)
        sidx[u] = g_knn[(b*Nn + n0)*20 + u];
    __syncthreads();

    // phase A: gather-sum, 16 threads/row x LDG.128 (8 halves), fp32 accum
    // (per-element summation order identical to the LDG.32 version)
    int h = tid >> 4, o8 = tid & 15;
    for (int nl = h; nl < 32; nl += 16) {
        float a[8];
        #pragma unroll
        for (int e = 0; e < 8; ++e) a[e] = 0.f;
        #pragma unroll
        for (int k = 0; k < Kk; ++k) {
            int nb = sidx[nl*20 + k];          // global b*N+n index
            uint4 v = *(const uint4*)(g_hT + (size_t)nb*Cc + o8*8);
            __half2* h2 = (__half2*)&v;
            #pragma unroll
            for (int p = 0; p < 4; ++p) {
                float2 f = __half22float2(h2[p]);
                a[2*p]     += f.x;
                a[2*p + 1] += f.y;
            }
        }
        #pragma unroll
        for (int e = 0; e < 8; ++e) sm[nl][o8*8 + e] = a[e];
    }
    __syncthreads();

    // phase B: transposed, coalesced write with center + bias + shortcut
    int w = tid >> 5, l = tid & 31;
    int n = n0 + l;
    #pragma unroll
    for (int oo = 0; oo < 16; ++oo) {
        int o2b = w + oo*8;
        int off = (b*Cc + o2b)*Nn + n;
        float biasv = fmaf(20.f, bg[o2b], bc[o2b]);
        out[off] = (sm[l][o2b] + g_center[off] + biasv) * (1.0f / 21.0f) + points[off];
    }
}

// ------------------------- launch -----------------------------------------
extern "C" void kernel_launch(void* const* d_in, const int* in_sizes, int n_in,
                              void* d_out, int out_size) {
    const float* xyz    = (const float*)d_in[0];
    const float* points = (const float*)d_in[1];
    const float* Wc     = (const float*)d_in[2];
    const float* bc     = (const float*)d_in[3];
    const float* Wg     = (const float*)d_in[4];
    const float* bg     = (const float*)d_in[5];
    float* out = (float*)d_out;

    int knn_smem = Nn*16 + KTHR*(KSTG+1)*8;
    cudaFuncSetAttribute(knn_kernel, cudaFuncAttributeMaxDynamicSharedMemorySize, knn_smem);
    cudaFuncSetAttribute(gemm_kernel, cudaFuncAttributeMaxDynamicSharedMemorySize, GEMM_SMEM);

    knn_kernel<<<Bb*BPB, KTHR, knn_smem>>>(xyz);
    gemm_kernel<<<dim3(Nn/128, Bb, 2), 256, GEMM_SMEM>>>(points, Wc, Wg);
    combine_kernel<<<dim3(Nn/32, Bb), 256>>>(points, bc, bg, out);
}